// round 2
// baseline (speedup 1.0000x reference)
#include <cuda_runtime.h>
#include <cstdint>

// Row-wise top-k(=6) thresholded renormalization.
//   delta = (6th largest of row) + 1e-7
//   w     = max(v - delta, 0)
//   out   = w / (sum(w) + 1e-7)
//
// One block per row. 256 threads, one float4 (4 elems) per thread -> 1024 cols.
// Top-6 found by 6 rounds of warp-wide max extraction done in ordered-uint
// key space (redux.sync.max.u32 — fp32 redux is not available at this target).
// Exact duplicate handling: one instance removed per round by a
// ballot-elected leader. Hierarchical: per-warp top-6 -> 48 candidates ->
// warp 0 selects the 6th.

#define COLS 1024
#define TOPK 6
#define EPSV 1e-7f

__device__ __forceinline__ unsigned redux_max_u32(unsigned v) {
    unsigned r;
    asm volatile("redux.sync.max.u32 %0, %1, %2;"
                 : "=r"(r) : "r"(v), "r"(0xffffffffu));
    return r;
}

// monotone bijection: float ordering -> u32 ordering
__device__ __forceinline__ unsigned fkey(float f) {
    unsigned b = __float_as_uint(f);
    return b ^ ((unsigned)((int)b >> 31) | 0x80000000u);
}
// inverse (only ever applied to keys of real, finite data values)
__device__ __forceinline__ float funkey(unsigned k) {
    unsigned b = k ^ (~(k >> 31) + 1u | 0x80000000u);
    // simpler exact inverse:
    b = (k & 0x80000000u) ? (k ^ 0x80000000u) : ~k;
    return __uint_as_float(b);
}

__global__ __launch_bounds__(256, 8)
void topk_renorm_kernel(const float* __restrict__ in,
                        float* __restrict__ out) {
    const int row  = blockIdx.x;
    const int tid  = threadIdx.x;
    const int lane = tid & 31;
    const int warp = tid >> 5;

    __shared__ unsigned sh_top[64];   // 8 warps * 6 keys, padded to 64 with 0
    __shared__ float    sh_sum[8];
    __shared__ float    sh_delta;
    __shared__ float    sh_rinv;

    // pad slots [48,64) so warp 0's second operand is harmless
    if (tid >= 48 && tid < 64) sh_top[tid] = 0u;

    const float4* rp = reinterpret_cast<const float4*>(in + (size_t)row * COLS);
    float4 v = rp[tid];

    // ordered-uint working keys (destroyed by extraction; 0 == -inf sentinel)
    unsigned k0 = fkey(v.x), k1 = fkey(v.y), k2 = fkey(v.z), k3 = fkey(v.w);
    unsigned lmax = max(max(k0, k1), max(k2, k3));

    // ---- stage 1: per-warp top-6 via iterative extraction ----
#pragma unroll
    for (int r = 0; r < TOPK; ++r) {
        unsigned m = redux_max_u32(lmax);
        unsigned msk = __ballot_sync(0xffffffffu, lmax == m);
        if (lane == (__ffs((int)msk) - 1)) {
            // leader removes exactly one instance of m
            if      (k0 == m) k0 = 0u;
            else if (k1 == m) k1 = 0u;
            else if (k2 == m) k2 = 0u;
            else              k3 = 0u;
            lmax = max(max(k0, k1), max(k2, k3));
            sh_top[warp * TOPK + r] = m;
        }
    }
    __syncthreads();

    // ---- stage 2: warp 0 selects 6th largest of the 48 candidates ----
    if (warp == 0) {
        unsigned a = sh_top[lane];
        unsigned b = sh_top[lane + 32];
        unsigned lm = max(a, b);
        unsigned kth = 0u;
#pragma unroll
        for (int r = 0; r < TOPK; ++r) {
            unsigned m = redux_max_u32(lm);
            kth = m;
            unsigned msk = __ballot_sync(0xffffffffu, lm == m);
            if (lane == (__ffs((int)msk) - 1)) {
                if (a == m) a = 0u; else b = 0u;
                lm = max(a, b);
            }
        }
        if (lane == 0) sh_delta = funkey(kth) + EPSV;
    }
    __syncthreads();

    // ---- epilogue: clamp, sum, normalize, store ----
    const float delta = sh_delta;
    float w0 = fmaxf(v.x - delta, 0.0f);
    float w1 = fmaxf(v.y - delta, 0.0f);
    float w2 = fmaxf(v.z - delta, 0.0f);
    float w3 = fmaxf(v.w - delta, 0.0f);

    float s = (w0 + w1) + (w2 + w3);
#pragma unroll
    for (int o = 16; o > 0; o >>= 1)
        s += __shfl_xor_sync(0xffffffffu, s, o);
    if (lane == 0) sh_sum[warp] = s;
    __syncthreads();

    if (tid == 0) {
        float t = EPSV;
#pragma unroll
        for (int i = 0; i < 8; ++i) t += sh_sum[i];
        sh_rinv = 1.0f / t;
    }
    __syncthreads();

    const float rinv = sh_rinv;
    float4 o4;
    o4.x = w0 * rinv;
    o4.y = w1 * rinv;
    o4.z = w2 * rinv;
    o4.w = w3 * rinv;
    reinterpret_cast<float4*>(out + (size_t)row * COLS)[tid] = o4;
}

extern "C" void kernel_launch(void* const* d_in, const int* in_sizes, int n_in,
                              void* d_out, int out_size) {
    const float* in = (const float*)d_in[0];
    float* out = (float*)d_out;
    const int rows = in_sizes[0] / COLS;   // 65536 for the reference shape
    topk_renorm_kernel<<<rows, 256>>>(in, out);
}